// round 15
// baseline (speedup 1.0000x reference)
#include <cuda_runtime.h>
#include <cstdint>

#define NN 8192
#define KDIM 512
#define F 64
#define GEMM_BLOCKS 128
#define ROWS_PER_BLK 8
#define SCAN_THREADS 512
#define SCAN_BLOCKS (NN / ROWS_PER_BLK)   // 1024
#define CAP 512
#define NSTG 3
#define ROW_BYTES (NN * 4)                // 32768

// dynamic smem layout (scan kernel)
#define OFF_MBAR 0                        // 3 x 8B
#define OFF_IDX  64                       // CAP u16 = 1024B
#define OFF_PART 1088                     // 32*64 floats = 8192B
#define OFF_CNT  9280
#define OFF_DIAG 9288
#define OFF_BUF  9344                     // 3 x 32768
#define SCAN_SMEM (OFF_BUF + NSTG * ROW_BYTES)   // 107648

// ---- scratch (static; no allocations) ----
__device__ float        g_z[NN * F];               // 2 MB
__device__ float        g_zi[NN];
__device__ float        g_zj[NN];
__device__ float        g_S[F];
__device__ float        g_Spart[GEMM_BLOCKS * F];
__device__ unsigned int g_cnt_gemm;                // zero-init, self-resetting

__device__ __forceinline__ uint32_t smem_u32(const void* p) {
    uint32_t a;
    asm("{ .reg .u64 t; cvta.to.shared.u64 t, %1; cvt.u32.u64 %0, t; }" : "=r"(a) : "l"(p));
    return a;
}
#define MBARRIER_INIT(addr, cnt) \
    asm volatile("mbarrier.init.shared.b64 [%0], %1;" :: "r"(addr), "r"((uint32_t)(cnt)) : "memory")
#define MBARRIER_EXPECT_TX(addr, bytes) \
    asm volatile("mbarrier.arrive.expect_tx.shared.b64 _, [%0], %1;" :: "r"(addr), "r"((uint32_t)(bytes)) : "memory")
#define MBARRIER_WAIT_PARITY(addr, par) do {                                        \
    uint32_t _a = (addr); uint32_t _p = (uint32_t)(par); uint32_t _d;               \
    asm volatile("{\n\t.reg .pred p;\n\t"                                           \
        "mbarrier.try_wait.parity.acquire.cta.shared::cta.b64 p, [%1], %2;\n\t"     \
        "selp.b32 %0, 1, 0, p;\n\t}" : "=r"(_d) : "r"(_a), "r"(_p) : "memory");     \
    if (!_d) {                                                                      \
        asm volatile("{\n\t.reg .pred P1;\n\t"                                      \
            "WL_%=:\n\t"                                                            \
            "mbarrier.try_wait.parity.acquire.cta.shared::cta.b64 P1, [%0], %1, 0x989680;\n\t" \
            "@P1 bra.uni WD_%=;\n\tbra.uni WL_%=;\n\tWD_%=:\n\t}"                   \
            :: "r"(_a), "r"(_p) : "memory");                                        \
    }                                                                               \
} while (0)
#define BULK_CP(dst, src, bytes, mbar) \
    asm volatile("cp.async.bulk.shared::cluster.global.mbarrier::complete_tx::bytes [%0], [%1], %2, [%3];" \
                 :: "r"(dst), "l"(src), "r"((uint32_t)(bytes)), "r"(mbar) : "memory")

// ===========================================================================
// K1: GEMM z = X W^T + b (R6-exact, proven ~15us). PDL trigger at entry
// (consumers gridsync before reading z).
// ===========================================================================
__global__ void __launch_bounds__(256) gemm_kernel(
    const float* __restrict__ X, const float* __restrict__ W,
    const float* __restrict__ bias,
    const float* __restrict__ a1, const float* __restrict__ a2)
{
    cudaTriggerProgrammaticLaunchCompletion();

    __shared__ float Xs[64][36];
    __shared__ float Ws[32][68];
    __shared__ float sS[64];
    __shared__ int   s_last;

    const int t  = threadIdx.x;
    const int tx = t & 15;
    const int ty = t >> 4;
    const int row0 = blockIdx.x * 64;

    float acc[4][4] = {};
    const float4* X4 = (const float4*)X;
    const float4* W4 = (const float4*)W;

    for (int kc = 0; kc < KDIM; kc += 32) {
        __syncthreads();
        #pragma unroll
        for (int p = 0; p < 2; p++) {
            int idx = t + p * 256;
            int r = idx >> 3, q = idx & 7;
            float4 v = X4[(size_t)(row0 + r) * (KDIM / 4) + (kc >> 2) + q];
            *(float4*)&Xs[r][q * 4] = v;
        }
        #pragma unroll
        for (int p = 0; p < 2; p++) {
            int idx = t + p * 256;
            int o = idx >> 3, kq = idx & 7;
            float4 v = W4[o * (KDIM / 4) + (kc >> 2) + kq];
            Ws[kq * 4 + 0][o] = v.x;
            Ws[kq * 4 + 1][o] = v.y;
            Ws[kq * 4 + 2][o] = v.z;
            Ws[kq * 4 + 3][o] = v.w;
        }
        __syncthreads();

        #pragma unroll
        for (int k = 0; k < 32; k++) {
            float4 w = *(const float4*)&Ws[k][tx * 4];
            float x0 = Xs[ty * 4 + 0][k];
            float x1 = Xs[ty * 4 + 1][k];
            float x2 = Xs[ty * 4 + 2][k];
            float x3 = Xs[ty * 4 + 3][k];
            acc[0][0] += x0 * w.x; acc[0][1] += x0 * w.y; acc[0][2] += x0 * w.z; acc[0][3] += x0 * w.w;
            acc[1][0] += x1 * w.x; acc[1][1] += x1 * w.y; acc[1][2] += x1 * w.z; acc[1][3] += x1 * w.w;
            acc[2][0] += x2 * w.x; acc[2][1] += x2 * w.y; acc[2][2] += x2 * w.z; acc[2][3] += x2 * w.w;
            acc[3][0] += x3 * w.x; acc[3][1] += x3 * w.y; acc[3][2] += x3 * w.z; acc[3][3] += x3 * w.w;
        }
    }

    float4 bv = ((const float4*)bias)[tx];
    #pragma unroll
    for (int r = 0; r < 4; r++) {
        acc[r][0] += bv.x; acc[r][1] += bv.y; acc[r][2] += bv.z; acc[r][3] += bv.w;
    }

    float4 a1v = ((const float4*)a1)[tx];
    float4 a2v = ((const float4*)a2)[tx];

    #pragma unroll
    for (int r = 0; r < 4; r++) {
        int row = row0 + ty * 4 + r;
        float4 zr;
        zr.x = acc[r][0]; zr.y = acc[r][1]; zr.z = acc[r][2]; zr.w = acc[r][3];
        ((float4*)g_z)[row * 16 + tx] = zr;

        float pzi = a1v.x * zr.x + a1v.y * zr.y + a1v.z * zr.z + a1v.w * zr.w;
        float pzj = a2v.x * zr.x + a2v.y * zr.y + a2v.z * zr.z + a2v.w * zr.w;
        #pragma unroll
        for (int m = 8; m > 0; m >>= 1) {
            pzi += __shfl_xor_sync(0xffffffffu, pzi, m, 16);
            pzj += __shfl_xor_sync(0xffffffffu, pzj, m, 16);
        }
        if (tx == 0) { g_zi[row] = pzi; g_zj[row] = pzj; }
    }

    __syncthreads();
    if (t < 64) sS[t] = 0.0f;
    __syncthreads();
    #pragma unroll
    for (int c = 0; c < 4; c++) {
        float p = acc[0][c] + acc[1][c] + acc[2][c] + acc[3][c];
        atomicAdd(&sS[tx * 4 + c], p);
    }
    __syncthreads();
    if (t < 64) g_Spart[blockIdx.x * 64 + t] = sS[t];

    __threadfence();
    if (t == 0) {
        unsigned int old = atomicAdd(&g_cnt_gemm, 1u);
        s_last = (old == GEMM_BLOCKS - 1) ? 1 : 0;
        if (s_last) g_cnt_gemm = 0u;   // self-reset for graph replay
    }
    __syncthreads();
    if (s_last && t < 64) {
        float s = 0.0f;
        #pragma unroll 8
        for (int b = 0; b < GEMM_BLOCKS; b++)
            s += __ldcg(&g_Spart[b * 64 + t]);
        g_S[t] = s;
    }
}

// ===========================================================================
// K2: TMA-decoupled scan. cp.async.bulk streams adj rows into a 3-stage smem
// ring (no warp involvement); warps process rows from smem (compaction) and
// run gather+finalize WHILE the next rows stream in.
// ===========================================================================
#define PROCU(v, c, i) do {                                                        \
    if ((v.x | v.y | v.z | v.w) != 0u) {                                           \
        int j = (c) * 4;                                                           \
        if (v.x) { if (j     == (i)) *s_diag = 1; else { int q = atomicAdd(s_cnt, 1); if (q < CAP) s_idx[q] = (unsigned short)(j    ); } } \
        if (v.y) { if (j + 1 == (i)) *s_diag = 1; else { int q = atomicAdd(s_cnt, 1); if (q < CAP) s_idx[q] = (unsigned short)(j + 1); } } \
        if (v.z) { if (j + 2 == (i)) *s_diag = 1; else { int q = atomicAdd(s_cnt, 1); if (q < CAP) s_idx[q] = (unsigned short)(j + 2); } } \
        if (v.w) { if (j + 3 == (i)) *s_diag = 1; else { int q = atomicAdd(s_cnt, 1); if (q < CAP) s_idx[q] = (unsigned short)(j + 3); } } \
    }                                                                              \
} while (0)

__global__ void __launch_bounds__(SCAN_THREADS) scan_kernel(
    const float* __restrict__ adj, float* __restrict__ out)
{
    extern __shared__ __align__(128) char smem[];
    const uint32_t smb = smem_u32(smem);
    unsigned short* s_idx  = (unsigned short*)(smem + OFF_IDX);
    float*          s_part = (float*)(smem + OFF_PART);
    int*            s_cnt  = (int*)(smem + OFF_CNT);
    int*            s_diag = (int*)(smem + OFF_DIAG);

    const int t    = threadIdx.x;
    const int base = blockIdx.x * ROWS_PER_BLK;

    if (t == 0) {
        #pragma unroll
        for (int s = 0; s < NSTG; s++) MBARRIER_INIT(smb + OFF_MBAR + 8 * s, 1);
    }
    __syncthreads();
    if (t == 0) {
        #pragma unroll
        for (int s = 0; s < NSTG; s++) {
            uint32_t mb = smb + OFF_MBAR + 8 * s;
            MBARRIER_EXPECT_TX(mb, ROW_BYTES);
            BULK_CP(smb + OFF_BUF + s * ROW_BYTES,
                    adj + (size_t)(base + s) * NN, ROW_BYTES, mb);
        }
    }

    const int chunk = t & 15;    // float4 chunk of the 64-float z row
    const int group = t >> 4;    // 0..31
    const float4* z4 = (const float4*)g_z;

    #pragma unroll 1
    for (int r = 0; r < ROWS_PER_BLK; r++) {
        const int s = r % NSTG;
        const int i = base + r;
        MBARRIER_WAIT_PARITY(smb + OFF_MBAR + 8 * s, (r / NSTG) & 1);
        if (t == 0) { *s_cnt = 0; *s_diag = 0; }
        __syncthreads();

        // ---- process row from smem: 4 batched LDS.128 + compaction ----
        {
            const uint4* buf = (const uint4*)(smem + OFF_BUF + s * ROW_BYTES);
            uint4 v0 = buf[t          ];
            uint4 v1 = buf[t +  512   ];
            uint4 v2 = buf[t + 1024   ];
            uint4 v3 = buf[t + 1536   ];
            PROCU(v0, t          , i);
            PROCU(v1, t +  512   , i);
            PROCU(v2, t + 1024   , i);
            PROCU(v3, t + 1536   , i);
        }
        __syncthreads();   // cnt/idx final; buffer s free

        // ---- refill buffer s for row r+3 (streams during gather below) ----
        if (t == 0 && r + NSTG < ROWS_PER_BLK) {
            uint32_t mb = smb + OFF_MBAR + 8 * s;
            MBARRIER_EXPECT_TX(mb, ROW_BYTES);
            BULK_CP(smb + OFF_BUF + s * ROW_BYTES,
                    adj + (size_t)(base + r + NSTG) * NN, ROW_BYTES, mb);
        }

        if (r == 0) cudaGridDependencySynchronize();   // z/zi/zj/S ready

        // ---- gather T = sum z[neighbors] (L2), 2-way batched ----
        int cnt = *s_cnt; if (cnt > CAP) cnt = CAP;
        const int dg = *s_diag;

        float4 acc = make_float4(0.f, 0.f, 0.f, 0.f);
        int n = group;
        for (; n + 32 < cnt; n += 64) {
            int j0 = s_idx[n], j1 = s_idx[n + 32];
            float4 va = z4[j0 * 16 + chunk];
            float4 vb = z4[j1 * 16 + chunk];
            acc.x += va.x + vb.x; acc.y += va.y + vb.y;
            acc.z += va.z + vb.z; acc.w += va.w + vb.w;
        }
        if (n < cnt) {
            float4 va = z4[(int)s_idx[n] * 16 + chunk];
            acc.x += va.x; acc.y += va.y; acc.z += va.z; acc.w += va.w;
        }
        ((float4*)s_part)[group * 16 + chunk] = acc;
        __syncthreads();

        if (t < 64) {
            float T = 0.0f;
            #pragma unroll
            for (int g = 0; g < 32; g++) T += s_part[g * 64 + t];

            float zif = g_z[i * 64 + t];
            float zi  = g_zi[i];
            float zj  = g_zj[i];

            float v1 = zi > 0.0f ? zi : 0.01f * zi;      // leaky_relu
            float e1 = expf(v1);
            float e2 = 0.0f;
            if (dg) {
                float v2 = zi + zj;
                v2 = v2 > 0.0f ? v2 : 0.01f * v2;
                e2 = expf(v2);
            }
            float D   = (float)(NN - cnt - dg) + (float)cnt * e1 + (dg ? e2 : 0.0f);
            float num = g_S[t] + (e1 - 1.0f) * T + (dg ? (e2 - 1.0f) * zif : 0.0f);
            float h   = zif - num / D;
            out[i * 64 + t] = h > 0.0f ? h : 0.0f;
        }
        __syncthreads();   // part/idx reuse safety
    }
}

// ---------------------------------------------------------------------------
extern "C" void kernel_launch(void* const* d_in, const int* in_sizes, int n_in,
                              void* d_out, int out_size) {
    const float* X   = (const float*)d_in[0];  // (8192, 512)
    const float* adj = (const float*)d_in[1];  // (8192, 8192)
    // d_in[2] = eye_matrix — unused (identity known analytically)
    const float* W   = (const float*)d_in[3];  // (64, 512)
    const float* b   = (const float*)d_in[4];  // (64,)
    const float* a1  = (const float*)d_in[5];  // (1, 64)
    const float* a2  = (const float*)d_in[6];  // (1, 64)
    float* out = (float*)d_out;                // (8192, 64)

    cudaFuncSetAttribute(scan_kernel, cudaFuncAttributeMaxDynamicSharedMemorySize, SCAN_SMEM);

    gemm_kernel<<<GEMM_BLOCKS, 256>>>(X, W, b, a1, a2);

    cudaLaunchConfig_t cfg = {};
    cfg.gridDim  = dim3(SCAN_BLOCKS, 1, 1);
    cfg.blockDim = dim3(SCAN_THREADS, 1, 1);
    cfg.dynamicSmemBytes = SCAN_SMEM;
    cfg.stream = 0;
    cudaLaunchAttribute attrs[1];
    attrs[0].id = cudaLaunchAttributeProgrammaticStreamSerialization;
    attrs[0].val.programmaticStreamSerializationAllowed = 1;
    cfg.attrs = attrs;
    cfg.numAttrs = 1;
    cudaLaunchKernelEx(&cfg, scan_kernel, adj, out);
}

// round 16
// speedup vs baseline: 1.6122x; 1.6122x over previous
#include <cuda_runtime.h>
#include <cuda_bf16.h>
#include <cstdint>

#define NN 8192
#define KDIM 512
#define F 64
#define GEMM_BLOCKS 128
#define ROWS_PER_BLK 8
#define SCAN_BLOCKS (NN / ROWS_PER_BLK)   // 1024
#define CAP 512

// ---- scratch (static; no allocations) ----
__device__ float        g_z[NN * F];               // 2 MB fp32 (finalize reads)
__device__ uint32_t     g_zh[NN * (F / 2)];        // 1 MB bf16x2 shadow (gather reads)
__device__ float        g_zi[NN];
__device__ float        g_zj[NN];
__device__ float        g_S[F];
__device__ float        g_Spart[GEMM_BLOCKS * F];
__device__ unsigned int g_cnt_gemm;                // zero-init, self-resetting

__device__ __forceinline__ uint32_t pack_bf16(float lo, float hi) {
    uint32_t d;
    asm("cvt.rn.bf16x2.f32 %0, %1, %2;" : "=r"(d) : "f"(hi), "f"(lo));
    return d;
}

// ===========================================================================
// K1: GEMM z = X W^T + b (R6-exact config). Epilogue: zi/zj, colsum S,
// g_z fp32 + g_zh bf16 shadow. PDL trigger at entry.
// ===========================================================================
__global__ void __launch_bounds__(256) gemm_kernel(
    const float* __restrict__ X, const float* __restrict__ W,
    const float* __restrict__ bias,
    const float* __restrict__ a1, const float* __restrict__ a2)
{
    cudaTriggerProgrammaticLaunchCompletion();

    __shared__ float Xs[64][36];   // 64 rows x 32 k (+pad)
    __shared__ float Ws[32][68];   // 32 k x 64 cols (+pad)
    __shared__ float sS[64];
    __shared__ int   s_last;

    const int t  = threadIdx.x;
    const int tx = t & 15;          // cols tx*4 .. tx*4+3
    const int ty = t >> 4;          // rows ty*4 .. ty*4+3
    const int row0 = blockIdx.x * 64;

    float acc[4][4] = {};
    const float4* X4 = (const float4*)X;
    const float4* W4 = (const float4*)W;

    for (int kc = 0; kc < KDIM; kc += 32) {
        __syncthreads();
        #pragma unroll
        for (int p = 0; p < 2; p++) {
            int idx = t + p * 256;
            int r = idx >> 3, q = idx & 7;
            float4 v = X4[(size_t)(row0 + r) * (KDIM / 4) + (kc >> 2) + q];
            *(float4*)&Xs[r][q * 4] = v;
        }
        #pragma unroll
        for (int p = 0; p < 2; p++) {
            int idx = t + p * 256;
            int o = idx >> 3, kq = idx & 7;
            float4 v = W4[o * (KDIM / 4) + (kc >> 2) + kq];
            Ws[kq * 4 + 0][o] = v.x;
            Ws[kq * 4 + 1][o] = v.y;
            Ws[kq * 4 + 2][o] = v.z;
            Ws[kq * 4 + 3][o] = v.w;
        }
        __syncthreads();

        #pragma unroll
        for (int k = 0; k < 32; k++) {
            float4 w = *(const float4*)&Ws[k][tx * 4];
            float x0 = Xs[ty * 4 + 0][k];
            float x1 = Xs[ty * 4 + 1][k];
            float x2 = Xs[ty * 4 + 2][k];
            float x3 = Xs[ty * 4 + 3][k];
            acc[0][0] += x0 * w.x; acc[0][1] += x0 * w.y; acc[0][2] += x0 * w.z; acc[0][3] += x0 * w.w;
            acc[1][0] += x1 * w.x; acc[1][1] += x1 * w.y; acc[1][2] += x1 * w.z; acc[1][3] += x1 * w.w;
            acc[2][0] += x2 * w.x; acc[2][1] += x2 * w.y; acc[2][2] += x2 * w.z; acc[2][3] += x2 * w.w;
            acc[3][0] += x3 * w.x; acc[3][1] += x3 * w.y; acc[3][2] += x3 * w.z; acc[3][3] += x3 * w.w;
        }
    }

    float4 bv = ((const float4*)bias)[tx];
    #pragma unroll
    for (int r = 0; r < 4; r++) {
        acc[r][0] += bv.x; acc[r][1] += bv.y; acc[r][2] += bv.z; acc[r][3] += bv.w;
    }

    float4 a1v = ((const float4*)a1)[tx];
    float4 a2v = ((const float4*)a2)[tx];

    #pragma unroll
    for (int r = 0; r < 4; r++) {
        int row = row0 + ty * 4 + r;
        float4 zr;
        zr.x = acc[r][0]; zr.y = acc[r][1]; zr.z = acc[r][2]; zr.w = acc[r][3];
        ((float4*)g_z)[row * 16 + tx] = zr;

        // bf16 shadow for the gather (uint2 = 4 cols)
        uint2 uh;
        uh.x = pack_bf16(zr.x, zr.y);
        uh.y = pack_bf16(zr.z, zr.w);
        ((uint2*)g_zh)[row * 16 + tx] = uh;

        float pzi = a1v.x * zr.x + a1v.y * zr.y + a1v.z * zr.z + a1v.w * zr.w;
        float pzj = a2v.x * zr.x + a2v.y * zr.y + a2v.z * zr.z + a2v.w * zr.w;
        #pragma unroll
        for (int m = 8; m > 0; m >>= 1) {
            pzi += __shfl_xor_sync(0xffffffffu, pzi, m, 16);
            pzj += __shfl_xor_sync(0xffffffffu, pzj, m, 16);
        }
        if (tx == 0) { g_zi[row] = pzi; g_zj[row] = pzj; }
    }

    __syncthreads();
    if (t < 64) sS[t] = 0.0f;
    __syncthreads();
    #pragma unroll
    for (int c = 0; c < 4; c++) {
        float p = acc[0][c] + acc[1][c] + acc[2][c] + acc[3][c];
        atomicAdd(&sS[tx * 4 + c], p);
    }
    __syncthreads();
    if (t < 64) g_Spart[blockIdx.x * 64 + t] = sS[t];

    __threadfence();
    if (t == 0) {
        unsigned int old = atomicAdd(&g_cnt_gemm, 1u);
        s_last = (old == GEMM_BLOCKS - 1) ? 1 : 0;
        if (s_last) g_cnt_gemm = 0u;   // self-reset for graph replay
    }
    __syncthreads();
    if (s_last && t < 64) {
        float s = 0.0f;
        #pragma unroll 8
        for (int b = 0; b < GEMM_BLOCKS; b++)
            s += __ldcg(&g_Spart[b * 64 + t]);
        g_S[t] = s;
    }
}

// ===========================================================================
// K2: R6-exact scan (8 rows/block, 8 batched LDG.128, compaction), then
// grid-dep sync, then gather from bf16 shadow (halved L2 traffic, 2-way
// unrolled), closed-form finalize from fp32 z.
// ===========================================================================
#define PROC(v, c, i, r) do {                                                     \
    int j = (c) * 4;                                                              \
    if (v.x != 0.0f) { if (j     == (i)) s_diag[r] = 1; else { int q = atomicAdd(&s_cnt[r], 1); if (q < CAP) s_idx[r][q] = (unsigned short)(j    ); } } \
    if (v.y != 0.0f) { if (j + 1 == (i)) s_diag[r] = 1; else { int q = atomicAdd(&s_cnt[r], 1); if (q < CAP) s_idx[r][q] = (unsigned short)(j + 1); } } \
    if (v.z != 0.0f) { if (j + 2 == (i)) s_diag[r] = 1; else { int q = atomicAdd(&s_cnt[r], 1); if (q < CAP) s_idx[r][q] = (unsigned short)(j + 2); } } \
    if (v.w != 0.0f) { if (j + 3 == (i)) s_diag[r] = 1; else { int q = atomicAdd(&s_cnt[r], 1); if (q < CAP) s_idx[r][q] = (unsigned short)(j + 3); } } \
} while (0)

__global__ void __launch_bounds__(256) scan_gather_kernel(
    const float* __restrict__ adj, float* __restrict__ out)
{
    __shared__ unsigned short s_idx[ROWS_PER_BLK][CAP];   // 8 KB
    __shared__ float s_part[16 * 64];                     // 4 KB
    __shared__ int   s_cnt[ROWS_PER_BLK];
    __shared__ int   s_diag[ROWS_PER_BLK];

    const int t = threadIdx.x;
    const int base = blockIdx.x * ROWS_PER_BLK;
    if (t < ROWS_PER_BLK) { s_cnt[t] = 0; s_diag[t] = 0; }
    __syncthreads();

    // -------- scan phase: 8 rows, all 8 LDG.128 batched before processing ----
    #pragma unroll 1
    for (int r = 0; r < ROWS_PER_BLK; r++) {
        const int i = base + r;
        const float4* arow = (const float4*)(adj + (size_t)i * NN);
        float4 v0 = __ldcs(arow + t          );
        float4 v1 = __ldcs(arow + t + 1 * 256);
        float4 v2 = __ldcs(arow + t + 2 * 256);
        float4 v3 = __ldcs(arow + t + 3 * 256);
        float4 v4 = __ldcs(arow + t + 4 * 256);
        float4 v5 = __ldcs(arow + t + 5 * 256);
        float4 v6 = __ldcs(arow + t + 6 * 256);
        float4 v7 = __ldcs(arow + t + 7 * 256);
        PROC(v0, t          , i, r);
        PROC(v1, t + 1 * 256, i, r);
        PROC(v2, t + 2 * 256, i, r);
        PROC(v3, t + 3 * 256, i, r);
        PROC(v4, t + 4 * 256, i, r);
        PROC(v5, t + 5 * 256, i, r);
        PROC(v6, t + 6 * 256, i, r);
        PROC(v7, t + 7 * 256, i, r);
    }
    __syncthreads();

    // -------- wait for GEMM grid (usually already complete) ------------------
    cudaGridDependencySynchronize();

    // -------- gather from bf16 shadow + finalize ------------------------------
    const int chunk = t & 15;    // uint2 chunk (4 cols) of the 64-col z row
    const int group = t >> 4;
    const uint2* zh2 = (const uint2*)g_zh;

    #pragma unroll 1
    for (int r = 0; r < ROWS_PER_BLK; r++) {
        int cnt = s_cnt[r]; if (cnt > CAP) cnt = CAP;
        const int dg = s_diag[r];
        const int i  = base + r;

        float4 acc = make_float4(0.f, 0.f, 0.f, 0.f);
        int n = group;
        for (; n + 16 < cnt; n += 32) {
            uint2 ua = zh2[(int)s_idx[r][n]      * 16 + chunk];
            uint2 ub = zh2[(int)s_idx[r][n + 16] * 16 + chunk];
            float2 a0 = __bfloat1622float2(*(__nv_bfloat162*)&ua.x);
            float2 a1 = __bfloat1622float2(*(__nv_bfloat162*)&ua.y);
            float2 b0 = __bfloat1622float2(*(__nv_bfloat162*)&ub.x);
            float2 b1 = __bfloat1622float2(*(__nv_bfloat162*)&ub.y);
            acc.x += a0.x + b0.x; acc.y += a0.y + b0.y;
            acc.z += a1.x + b1.x; acc.w += a1.y + b1.y;
        }
        if (n < cnt) {
            uint2 ua = zh2[(int)s_idx[r][n] * 16 + chunk];
            float2 a0 = __bfloat1622float2(*(__nv_bfloat162*)&ua.x);
            float2 a1 = __bfloat1622float2(*(__nv_bfloat162*)&ua.y);
            acc.x += a0.x; acc.y += a0.y;
            acc.z += a1.x; acc.w += a1.y;
        }
        ((float4*)s_part)[group * 16 + chunk] = acc;
        __syncthreads();

        if (t < 64) {
            float T = 0.0f;
            #pragma unroll
            for (int g = 0; g < 16; g++) T += s_part[g * 64 + t];

            float zif = g_z[i * 64 + t];
            float zi  = g_zi[i];
            float zj  = g_zj[i];

            float v1 = zi > 0.0f ? zi : 0.01f * zi;      // leaky_relu
            float e1 = expf(v1);
            float e2 = 0.0f;
            if (dg) {
                float v2 = zi + zj;
                v2 = v2 > 0.0f ? v2 : 0.01f * v2;
                e2 = expf(v2);
            }
            float D   = (float)(NN - cnt - dg) + (float)cnt * e1 + (dg ? e2 : 0.0f);
            float num = g_S[t] + (e1 - 1.0f) * T + (dg ? (e2 - 1.0f) * zif : 0.0f);
            float h   = zif - num / D;
            out[i * 64 + t] = h > 0.0f ? h : 0.0f;
        }
        __syncthreads();
    }
}

// ---------------------------------------------------------------------------
extern "C" void kernel_launch(void* const* d_in, const int* in_sizes, int n_in,
                              void* d_out, int out_size) {
    const float* X   = (const float*)d_in[0];  // (8192, 512)
    const float* adj = (const float*)d_in[1];  // (8192, 8192)
    // d_in[2] = eye_matrix — unused (identity known analytically)
    const float* W   = (const float*)d_in[3];  // (64, 512)
    const float* b   = (const float*)d_in[4];  // (64,)
    const float* a1  = (const float*)d_in[5];  // (1, 64)
    const float* a2  = (const float*)d_in[6];  // (1, 64)
    float* out = (float*)d_out;                // (8192, 64)

    // Primary: GEMM (triggers programmatic completion at entry)
    gemm_kernel<<<GEMM_BLOCKS, 256>>>(X, W, b, a1, a2);

    // Secondary: scan+gather, overlapped via PDL
    cudaLaunchConfig_t cfg = {};
    cfg.gridDim  = dim3(SCAN_BLOCKS, 1, 1);
    cfg.blockDim = dim3(256, 1, 1);
    cfg.dynamicSmemBytes = 0;
    cfg.stream = 0;
    cudaLaunchAttribute attrs[1];
    attrs[0].id = cudaLaunchAttributeProgrammaticStreamSerialization;
    attrs[0].val.programmaticStreamSerializationAllowed = 1;
    cfg.attrs = attrs;
    cfg.numAttrs = 1;
    cudaLaunchKernelEx(&cfg, scan_gather_kernel, adj, out);
}